// round 16
// baseline (speedup 1.0000x reference)
#include <cuda_runtime.h>
#include <math.h>

#define IMG_H 192
#define IMG_W 192
#define TANFOVX 0.5f
#define TANFOVY 0.5f
#define SCALE_MOD 1.0f
#define NEAR_Z 0.2f
#define ALPHA_MIN (1.0f / 255.0f)
#define T_EPS 1.0e-4f
#define PMAX 256
#define TILE 16

// Single fused kernel (R13 champion structure): 144 blocks x 256 threads,
// 16x16 tiles, thread t preprocesses gaussian t; cull -> sort survivors ->
// composite. Branch-free composite body, radii chain only in block 0,
// compaction atomic inlined into preprocess, bg hoisted ahead of preprocess.
__global__ void __launch_bounds__(256) fused_kernel(const float* __restrict__ means3D,
                                                    const float* __restrict__ opac,
                                                    const float* __restrict__ colors,
                                                    const float* __restrict__ scales,
                                                    const float* __restrict__ rots,
                                                    const float* __restrict__ vm,
                                                    const float* __restrict__ pm,
                                                    const float* __restrict__ bg,
                                                    float* __restrict__ out,
                                                    int P) {
    __shared__ float4 s_a[PMAX];    // px, py, -0.5*conA, -conB   (original index)
    __shared__ float4 s_b[PMAX];    // -0.5*conC, op, thr, depth
    __shared__ float4 s_c[PMAX];    // cr, cg, cb
    __shared__ float4 s_sa[PMAX];   // sorted survivors
    __shared__ float4 s_sb[PMAX];
    __shared__ float4 s_sc[PMAX];
    __shared__ int    s_surv[PMAX];
    __shared__ int    s_n;

    const int tid = threadIdx.x;
    const int i = tid;

    if (tid == 0) s_n = 0;
    __syncthreads();  // warps still aligned at kernel start: near-free

    const int tiles_x = IMG_W / TILE;
    const int tile_x = blockIdx.x % tiles_x;
    const int tile_y = blockIdx.x / tiles_x;
    const float tx0 = (float)(tile_x * TILE) - 0.5f;
    const float tx1 = (float)(tile_x * TILE + TILE - 1) + 0.5f;
    const float ty0 = (float)(tile_y * TILE) - 0.5f;
    const float ty1 = (float)(tile_y * TILE + TILE - 1) + 0.5f;

    // bg loaded early: LDG latency hidden under the preprocess phase
    const float bg0 = bg[0], bg1 = bg[1], bg2 = bg[2];

    // ---------------- per-gaussian preprocess (thread i -> gaussian i) ------
    if (i < P) {
        // matrices as float4 rows (8 LDG.128 instead of ~30 LDG.32)
        const float4* vmv = (const float4*)vm;
        const float4* pmv = (const float4*)pm;
        float4 v0 = vmv[0], v1 = vmv[1], v2 = vmv[2], v3 = vmv[3];
        float4 p0 = pmv[0], p1 = pmv[1], p2 = pmv[2], p3 = pmv[3];

        float m0 = means3D[3 * i + 0];
        float m1 = means3D[3 * i + 1];
        float m2 = means3D[3 * i + 2];

        // p_view = m @ V[:3,:3] + V[3,:3]   (row-vector convention)
        float pv0 = m0 * v0.x + m1 * v1.x + m2 * v2.x + v3.x;
        float pv1 = m0 * v0.y + m1 * v1.y + m2 * v2.y + v3.y;
        float pv2 = m0 * v0.z + m1 * v1.z + m2 * v2.z + v3.z;

        // p_hom = [m,1] @ P (4x4)
        float ph0 = m0 * p0.x + m1 * p1.x + m2 * p2.x + p3.x;
        float ph1 = m0 * p0.y + m1 * p1.y + m2 * p2.y + p3.y;
        float ph3 = m0 * p0.w + m1 * p1.w + m2 * p2.w + p3.w;
        float pwinv = __fdividef(1.f, ph3 + 1e-7f);
        float ppx = ph0 * pwinv;
        float ppy = ph1 * pwinv;

        float depth = pv2;
        bool in_frustum = depth > NEAR_Z;

        // quaternion -> rotation (vector load, normalize via rsqrt)
        float4 q = ((const float4*)rots)[i];
        float qinv = rsqrtf(q.x * q.x + q.y * q.y + q.z * q.z + q.w * q.w);
        float q0 = q.x * qinv, q1 = q.y * qinv, q2 = q.z * qinv, q3 = q.w * qinv;
        float R00 = 1.f - 2.f * (q2 * q2 + q3 * q3);
        float R01 = 2.f * (q1 * q2 - q0 * q3);
        float R02 = 2.f * (q1 * q3 + q0 * q2);
        float R10 = 2.f * (q1 * q2 + q0 * q3);
        float R11 = 1.f - 2.f * (q1 * q1 + q3 * q3);
        float R12 = 2.f * (q2 * q3 - q0 * q1);
        float R20 = 2.f * (q1 * q3 - q0 * q2);
        float R21 = 2.f * (q2 * q3 + q0 * q1);
        float R22 = 1.f - 2.f * (q1 * q1 + q2 * q2);

        float s0 = SCALE_MOD * scales[3 * i + 0]; s0 = s0 * s0;
        float s1 = SCALE_MOD * scales[3 * i + 1]; s1 = s1 * s1;
        float s2v = SCALE_MOD * scales[3 * i + 2]; s2v = s2v * s2v;

        // Sigma = R diag(s2) R^T  (symmetric)
        float S00 = R00 * R00 * s0 + R01 * R01 * s1 + R02 * R02 * s2v;
        float S01 = R00 * R10 * s0 + R01 * R11 * s1 + R02 * R12 * s2v;
        float S02 = R00 * R20 * s0 + R01 * R21 * s1 + R02 * R22 * s2v;
        float S11 = R10 * R10 * s0 + R11 * R11 * s1 + R12 * R12 * s2v;
        float S12 = R10 * R20 * s0 + R11 * R21 * s1 + R12 * R22 * s2v;
        float S22 = R20 * R20 * s0 + R21 * R21 * s1 + R22 * R22 * s2v;

        float tz = in_frustum ? depth : 1.f;
        float tzinv = __fdividef(1.f, tz);
        float lx = 1.3f * TANFOVX, ly = 1.3f * TANFOVY;
        float tx = fminf(fmaxf(pv0 * tzinv, -lx), lx) * tz;
        float ty = fminf(fmaxf(pv1 * tzinv, -ly), ly) * tz;
        const float fx = IMG_W / (2.0f * TANFOVX);
        const float fy = IMG_H / (2.0f * TANFOVY);
        float J00 = fx * tzinv, J02 = -fx * tx * tzinv * tzinv;
        float J11 = fy * tzinv, J12 = -fy * ty * tzinv * tzinv;

        // Tm = J @ V^T
        float T00 = J00 * v0.x + J02 * v0.z;
        float T01 = J00 * v1.x + J02 * v1.z;
        float T02 = J00 * v2.x + J02 * v2.z;
        float T10 = J11 * v0.y + J12 * v0.z;
        float T11 = J11 * v1.y + J12 * v1.z;
        float T12 = J11 * v2.y + J12 * v2.z;

        // cov2d = Tm Sigma Tm^T
        float a0 = S00 * T00 + S01 * T01 + S02 * T02;
        float a1 = S01 * T00 + S11 * T01 + S12 * T02;
        float a2 = S02 * T00 + S12 * T01 + S22 * T02;
        float b0 = S00 * T10 + S01 * T11 + S02 * T12;
        float b1 = S01 * T10 + S11 * T11 + S12 * T12;
        float b2 = S02 * T10 + S12 * T11 + S22 * T12;
        float cov00 = T00 * a0 + T01 * a1 + T02 * a2;
        float cov01 = T10 * a0 + T11 * a1 + T12 * a2;
        float cov11 = T10 * b0 + T11 * b1 + T12 * b2;

        float c00 = cov00 + 0.3f;
        float c11 = cov11 + 0.3f;
        float c01 = cov01;
        float det = c00 * c11 - c01 * c01;
        bool valid = in_frustum && (det > 0.f);
        float detinv = __fdividef(1.f, (det > 0.f) ? det : 1.f);
        float conA = c11 * detinv;
        float conB = -c01 * detinv;
        float conC = c00 * detinv;

        float pxp = ((ppx + 1.0f) * IMG_W - 1.0f) * 0.5f;
        float pyp = ((ppy + 1.0f) * IMG_H - 1.0f) * 0.5f;

        float op = opac[i];
        // contribute only when power >= log(ALPHA_MIN/op); slack covers fp jitter,
        // exact alpha test re-applied in composite.
        float thr = valid ? (__logf(__fdividef(ALPHA_MIN, op)) - 1e-3f) : 3.0e38f;

        bool pred = false;
        if (valid && thr < 0.f) {
            // level set power == thr has max |dx| = sqrt(-2*thr*c00) (conic^-1 = cov)
            float ext_x = sqrtf(-2.f * thr * c00) + 1.0f;  // +1px safety margin
            float ext_y = sqrtf(-2.f * thr * c11) + 1.0f;
            pred = (pxp - ext_x <= tx1) && (pxp + ext_x >= tx0) &&
                   (pyp - ext_y <= ty1) && (pyp + ext_y >= ty0);
        }

        s_a[i] = make_float4(pxp, pyp, -0.5f * conA, -conB);
        s_b[i] = make_float4(-0.5f * conC, op, thr, depth);
        s_c[i] = make_float4(colors[3 * i + 0], colors[3 * i + 1], colors[3 * i + 2], 0.f);

        // order-free compaction inline (sort below keys on (depth, idx))
        if (pred) {
            int pos = atomicAdd(&s_n, 1);
            s_surv[pos] = i;
        }

        // radii output: only block 0 pays for this chain
        if (blockIdx.x == 0) {
            float mid = 0.5f * (c00 + c11);
            float lam1 = mid + sqrtf(fmaxf(0.1f, mid * mid - det));
            int radii = valid ? (int)ceilf(3.0f * sqrtf(lam1)) : 0;
            out[3 * IMG_H * IMG_W + i] = (float)radii;
        }
    }

    __syncthreads();
    const int n = s_n;

    // ------- stable depth rank among survivors; copy into sorted arrays -----
    if (tid < n) {
        int my = s_surv[tid];
        float myd = s_b[my].w;
        int rank = 0;
        #pragma unroll 4
        for (int k = 0; k < n; k++) {
            int ok = s_surv[k];
            float dk = s_b[ok].w;
            rank += (dk < myd) || (dk == myd && ok < my);
        }
        s_sa[rank] = s_a[my];
        s_sb[rank] = s_b[my];
        s_sc[rank] = s_c[my];
    }
    __syncthreads();

    // ---------------- per-pixel front-to-back composite (branch-free) -------
    const int px_i = tile_x * TILE + (tid & (TILE - 1));
    const int py_i = tile_y * TILE + (tid >> 4);
    const float xp = (float)px_i;
    const float yp = (float)py_i;

    float T = 1.0f;
    float accr = 0.f, accg = 0.f, accb = 0.f;
    bool done = false;

    int j = 0;
    for (; j + 4 <= n; j += 4) {
        #pragma unroll
        for (int u = 0; u < 4; u++) {
            float4 ga = s_sa[j + u];  // px,py,nA,nB
            float4 gb = s_sb[j + u];  // nC,op,thr
            float4 gc = s_sc[j + u];  // cr,cg,cb
            float dx = ga.x - xp;
            float dy = ga.y - yp;
            float power = fmaf(ga.z, dx * dx, fmaf(gb.x, dy * dy, ga.w * (dx * dy)));
            float av = fminf(0.99f, gb.y * __expf(power));
            bool on = (power <= 0.f) & (power >= gb.z) & (av >= ALPHA_MIN);
            float a = on ? av : 0.f;
            float test = T * (1.0f - a);
            bool live = !done && (test >= T_EPS);
            float w = live ? a * T : 0.f;
            accr = fmaf(w, gc.x, accr);
            accg = fmaf(w, gc.y, accg);
            accb = fmaf(w, gc.z, accb);
            T = live ? test : T;           // a==0 => test==T, so exact
            done = done || (test < T_EPS);
        }
        if (done) break;
    }
    for (; j < n; j++) {
        float4 ga = s_sa[j];
        float4 gb = s_sb[j];
        float4 gc = s_sc[j];
        float dx = ga.x - xp;
        float dy = ga.y - yp;
        float power = fmaf(ga.z, dx * dx, fmaf(gb.x, dy * dy, ga.w * (dx * dy)));
        float av = fminf(0.99f, gb.y * __expf(power));
        bool on = (power <= 0.f) & (power >= gb.z) & (av >= ALPHA_MIN);
        float a = on ? av : 0.f;
        float test = T * (1.0f - a);
        bool live = !done && (test >= T_EPS);
        float w = live ? a * T : 0.f;
        accr = fmaf(w, gc.x, accr);
        accg = fmaf(w, gc.y, accg);
        accb = fmaf(w, gc.z, accb);
        T = live ? test : T;
        done = done || (test < T_EPS);
    }

    const int HW = IMG_H * IMG_W;
    const int pix = py_i * IMG_W + px_i;
    out[pix]          = accr + bg0 * T;
    out[HW + pix]     = accg + bg1 * T;
    out[2 * HW + pix] = accb + bg2 * T;
}

extern "C" void kernel_launch(void* const* d_in, const int* in_sizes, int n_in,
                              void* d_out, int out_size) {
    const float* means3D = (const float*)d_in[0];
    // d_in[1] = means2D (unused by reference)
    const float* opac    = (const float*)d_in[2];
    const float* colors  = (const float*)d_in[3];
    const float* scales  = (const float*)d_in[4];
    const float* rots    = (const float*)d_in[5];
    const float* bg      = (const float*)d_in[6];
    const float* vm      = (const float*)d_in[7];
    const float* pm      = (const float*)d_in[8];
    float* out = (float*)d_out;

    int P = in_sizes[0] / 3;
    if (P > PMAX) P = PMAX;

    const int tiles = (IMG_W / TILE) * (IMG_H / TILE);
    fused_kernel<<<tiles, TILE * TILE>>>(means3D, opac, colors, scales, rots,
                                         vm, pm, bg, out, P);
}

// round 17
// speedup vs baseline: 1.1780x; 1.1780x over previous
#include <cuda_runtime.h>
#include <math.h>

#define IMG_H 192
#define IMG_W 192
#define TANFOVX 0.5f
#define TANFOVY 0.5f
#define SCALE_MOD 1.0f
#define NEAR_Z 0.2f
#define ALPHA_MIN (1.0f / 255.0f)
#define T_EPS 1.0e-4f
#define PMAX 256
#define TILE 16
#define LOG2E 1.4426950408889634f

// Single fused kernel (R13 champion structure): 144 blocks x 256 threads,
// 16x16 tiles, thread t preprocesses gaussian t; cull -> sort survivors ->
// composite. R17: log2(e) folded into the conic so the composite uses a bare
// exp2f (MUFU.EX2) instead of __expf's mul+EX2 — one fewer dependent FMUL
// per iteration; comparisons order-preserved (log2e > 0).
__global__ void __launch_bounds__(256) fused_kernel(const float* __restrict__ means3D,
                                                    const float* __restrict__ opac,
                                                    const float* __restrict__ colors,
                                                    const float* __restrict__ scales,
                                                    const float* __restrict__ rots,
                                                    const float* __restrict__ vm,
                                                    const float* __restrict__ pm,
                                                    const float* __restrict__ bg,
                                                    float* __restrict__ out,
                                                    int P) {
    __shared__ float4 s_a[PMAX];    // px, py, -0.5*conA*log2e, -conB*log2e
    __shared__ float4 s_b[PMAX];    // -0.5*conC*log2e, op, thr*log2e, depth
    __shared__ float4 s_c[PMAX];    // cr, cg, cb
    __shared__ float4 s_sa[PMAX];   // sorted survivors
    __shared__ float4 s_sb[PMAX];
    __shared__ float4 s_sc[PMAX];
    __shared__ int    s_surv[PMAX];
    __shared__ int    s_n;

    const int tid = threadIdx.x;
    const int i = tid;

    if (tid == 0) s_n = 0;
    __syncthreads();  // warps still aligned at kernel start: near-free

    const int tiles_x = IMG_W / TILE;
    const int tile_x = blockIdx.x % tiles_x;
    const int tile_y = blockIdx.x / tiles_x;
    const float tx0 = (float)(tile_x * TILE) - 0.5f;
    const float tx1 = (float)(tile_x * TILE + TILE - 1) + 0.5f;
    const float ty0 = (float)(tile_y * TILE) - 0.5f;
    const float ty1 = (float)(tile_y * TILE + TILE - 1) + 0.5f;

    // ---------------- per-gaussian preprocess (thread i -> gaussian i) ------
    if (i < P) {
        // matrices as float4 rows (8 LDG.128 instead of ~30 LDG.32)
        const float4* vmv = (const float4*)vm;
        const float4* pmv = (const float4*)pm;
        float4 v0 = vmv[0], v1 = vmv[1], v2 = vmv[2], v3 = vmv[3];
        float4 p0 = pmv[0], p1 = pmv[1], p2 = pmv[2], p3 = pmv[3];

        float m0 = means3D[3 * i + 0];
        float m1 = means3D[3 * i + 1];
        float m2 = means3D[3 * i + 2];

        // p_view = m @ V[:3,:3] + V[3,:3]   (row-vector convention)
        float pv0 = m0 * v0.x + m1 * v1.x + m2 * v2.x + v3.x;
        float pv1 = m0 * v0.y + m1 * v1.y + m2 * v2.y + v3.y;
        float pv2 = m0 * v0.z + m1 * v1.z + m2 * v2.z + v3.z;

        // p_hom = [m,1] @ P (4x4)
        float ph0 = m0 * p0.x + m1 * p1.x + m2 * p2.x + p3.x;
        float ph1 = m0 * p0.y + m1 * p1.y + m2 * p2.y + p3.y;
        float ph3 = m0 * p0.w + m1 * p1.w + m2 * p2.w + p3.w;
        float pwinv = __fdividef(1.f, ph3 + 1e-7f);
        float ppx = ph0 * pwinv;
        float ppy = ph1 * pwinv;

        float depth = pv2;
        bool in_frustum = depth > NEAR_Z;

        // quaternion -> rotation (vector load, normalize via rsqrt)
        float4 q = ((const float4*)rots)[i];
        float qinv = rsqrtf(q.x * q.x + q.y * q.y + q.z * q.z + q.w * q.w);
        float q0 = q.x * qinv, q1 = q.y * qinv, q2 = q.z * qinv, q3 = q.w * qinv;
        float R00 = 1.f - 2.f * (q2 * q2 + q3 * q3);
        float R01 = 2.f * (q1 * q2 - q0 * q3);
        float R02 = 2.f * (q1 * q3 + q0 * q2);
        float R10 = 2.f * (q1 * q2 + q0 * q3);
        float R11 = 1.f - 2.f * (q1 * q1 + q3 * q3);
        float R12 = 2.f * (q2 * q3 - q0 * q1);
        float R20 = 2.f * (q1 * q3 - q0 * q2);
        float R21 = 2.f * (q2 * q3 + q0 * q1);
        float R22 = 1.f - 2.f * (q1 * q1 + q2 * q2);

        float s0 = SCALE_MOD * scales[3 * i + 0]; s0 = s0 * s0;
        float s1 = SCALE_MOD * scales[3 * i + 1]; s1 = s1 * s1;
        float s2v = SCALE_MOD * scales[3 * i + 2]; s2v = s2v * s2v;

        // Sigma = R diag(s2) R^T  (symmetric)
        float S00 = R00 * R00 * s0 + R01 * R01 * s1 + R02 * R02 * s2v;
        float S01 = R00 * R10 * s0 + R01 * R11 * s1 + R02 * R12 * s2v;
        float S02 = R00 * R20 * s0 + R01 * R21 * s1 + R02 * R22 * s2v;
        float S11 = R10 * R10 * s0 + R11 * R11 * s1 + R12 * R12 * s2v;
        float S12 = R10 * R20 * s0 + R11 * R21 * s1 + R12 * R22 * s2v;
        float S22 = R20 * R20 * s0 + R21 * R21 * s1 + R22 * R22 * s2v;

        float tz = in_frustum ? depth : 1.f;
        float tzinv = __fdividef(1.f, tz);
        float lx = 1.3f * TANFOVX, ly = 1.3f * TANFOVY;
        float tx = fminf(fmaxf(pv0 * tzinv, -lx), lx) * tz;
        float ty = fminf(fmaxf(pv1 * tzinv, -ly), ly) * tz;
        const float fx = IMG_W / (2.0f * TANFOVX);
        const float fy = IMG_H / (2.0f * TANFOVY);
        float J00 = fx * tzinv, J02 = -fx * tx * tzinv * tzinv;
        float J11 = fy * tzinv, J12 = -fy * ty * tzinv * tzinv;

        // Tm = J @ V^T
        float T00 = J00 * v0.x + J02 * v0.z;
        float T01 = J00 * v1.x + J02 * v1.z;
        float T02 = J00 * v2.x + J02 * v2.z;
        float T10 = J11 * v0.y + J12 * v0.z;
        float T11 = J11 * v1.y + J12 * v1.z;
        float T12 = J11 * v2.y + J12 * v2.z;

        // cov2d = Tm Sigma Tm^T
        float a0 = S00 * T00 + S01 * T01 + S02 * T02;
        float a1 = S01 * T00 + S11 * T01 + S12 * T02;
        float a2 = S02 * T00 + S12 * T01 + S22 * T02;
        float b0 = S00 * T10 + S01 * T11 + S02 * T12;
        float b1 = S01 * T10 + S11 * T11 + S12 * T12;
        float b2 = S02 * T10 + S12 * T11 + S22 * T12;
        float cov00 = T00 * a0 + T01 * a1 + T02 * a2;
        float cov01 = T10 * a0 + T11 * a1 + T12 * a2;
        float cov11 = T10 * b0 + T11 * b1 + T12 * b2;

        float c00 = cov00 + 0.3f;
        float c11 = cov11 + 0.3f;
        float c01 = cov01;
        float det = c00 * c11 - c01 * c01;
        bool valid = in_frustum && (det > 0.f);
        float detinv = __fdividef(1.f, (det > 0.f) ? det : 1.f);
        float conA = c11 * detinv;
        float conB = -c01 * detinv;
        float conC = c00 * detinv;

        float pxp = ((ppx + 1.0f) * IMG_W - 1.0f) * 0.5f;
        float pyp = ((ppy + 1.0f) * IMG_H - 1.0f) * 0.5f;

        float op = opac[i];
        // contribute only when power >= log(ALPHA_MIN/op); slack covers fp jitter,
        // exact alpha test re-applied in composite.
        float thr = valid ? (__logf(__fdividef(ALPHA_MIN, op)) - 1e-3f) : 3.0e38f;

        bool pred = false;
        if (valid && thr < 0.f) {
            // level set power == thr has max |dx| = sqrt(-2*thr*c00) (conic^-1 = cov)
            float ext_x = sqrtf(-2.f * thr * c00) + 1.0f;  // +1px safety margin
            float ext_y = sqrtf(-2.f * thr * c11) + 1.0f;
            pred = (pxp - ext_x <= tx1) && (pxp + ext_x >= tx0) &&
                   (pyp - ext_y <= ty1) && (pyp + ext_y >= ty0);
        }

        // log2e folded in: power2 = power*log2e, exp(power) == exp2(power2);
        // log2e > 0 preserves all sign/order comparisons.
        s_a[i] = make_float4(pxp, pyp, -0.5f * conA * LOG2E, -conB * LOG2E);
        s_b[i] = make_float4(-0.5f * conC * LOG2E, op, thr * LOG2E, depth);
        s_c[i] = make_float4(colors[3 * i + 0], colors[3 * i + 1], colors[3 * i + 2], 0.f);

        // order-free compaction inline (sort below keys on (depth, idx))
        if (pred) {
            int pos = atomicAdd(&s_n, 1);
            s_surv[pos] = i;
        }

        // radii output: only block 0 pays for this chain
        if (blockIdx.x == 0) {
            float mid = 0.5f * (c00 + c11);
            float lam1 = mid + sqrtf(fmaxf(0.1f, mid * mid - det));
            int radii = valid ? (int)ceilf(3.0f * sqrtf(lam1)) : 0;
            out[3 * IMG_H * IMG_W + i] = (float)radii;
        }
    }

    __syncthreads();
    const int n = s_n;

    // ------- stable depth rank among survivors; copy into sorted arrays -----
    if (tid < n) {
        int my = s_surv[tid];
        float myd = s_b[my].w;
        int rank = 0;
        #pragma unroll 4
        for (int k = 0; k < n; k++) {
            int ok = s_surv[k];
            float dk = s_b[ok].w;
            rank += (dk < myd) || (dk == myd && ok < my);
        }
        s_sa[rank] = s_a[my];
        s_sb[rank] = s_b[my];
        s_sc[rank] = s_c[my];
    }
    __syncthreads();

    // ---------------- per-pixel front-to-back composite (branch-free) -------
    const int px_i = tile_x * TILE + (tid & (TILE - 1));
    const int py_i = tile_y * TILE + (tid >> 4);
    const float xp = (float)px_i;
    const float yp = (float)py_i;

    float T = 1.0f;
    float accr = 0.f, accg = 0.f, accb = 0.f;
    bool done = false;

    int j = 0;
    for (; j + 4 <= n; j += 4) {
        #pragma unroll
        for (int u = 0; u < 4; u++) {
            float4 ga = s_sa[j + u];  // px,py,nA2,nB2 (log2e-scaled)
            float4 gb = s_sb[j + u];  // nC2,op,thr2
            float4 gc = s_sc[j + u];  // cr,cg,cb
            float dx = ga.x - xp;
            float dy = ga.y - yp;
            float power2 = fmaf(ga.z, dx * dx, fmaf(gb.x, dy * dy, ga.w * (dx * dy)));
            float av = fminf(0.99f, gb.y * exp2f(power2));
            bool on = (power2 <= 0.f) & (power2 >= gb.z) & (av >= ALPHA_MIN);
            float a = on ? av : 0.f;
            float test = T * (1.0f - a);
            bool live = !done && (test >= T_EPS);
            float w = live ? a * T : 0.f;
            accr = fmaf(w, gc.x, accr);
            accg = fmaf(w, gc.y, accg);
            accb = fmaf(w, gc.z, accb);
            T = live ? test : T;           // a==0 => test==T, so exact
            done = done || (test < T_EPS);
        }
        if (done) break;
    }
    for (; j < n; j++) {
        float4 ga = s_sa[j];
        float4 gb = s_sb[j];
        float4 gc = s_sc[j];
        float dx = ga.x - xp;
        float dy = ga.y - yp;
        float power2 = fmaf(ga.z, dx * dx, fmaf(gb.x, dy * dy, ga.w * (dx * dy)));
        float av = fminf(0.99f, gb.y * exp2f(power2));
        bool on = (power2 <= 0.f) & (power2 >= gb.z) & (av >= ALPHA_MIN);
        float a = on ? av : 0.f;
        float test = T * (1.0f - a);
        bool live = !done && (test >= T_EPS);
        float w = live ? a * T : 0.f;
        accr = fmaf(w, gc.x, accr);
        accg = fmaf(w, gc.y, accg);
        accb = fmaf(w, gc.z, accb);
        T = live ? test : T;
        done = done || (test < T_EPS);
    }

    const int HW = IMG_H * IMG_W;
    const int pix = py_i * IMG_W + px_i;
    out[pix]          = accr + bg[0] * T;
    out[HW + pix]     = accg + bg[1] * T;
    out[2 * HW + pix] = accb + bg[2] * T;
}

extern "C" void kernel_launch(void* const* d_in, const int* in_sizes, int n_in,
                              void* d_out, int out_size) {
    const float* means3D = (const float*)d_in[0];
    // d_in[1] = means2D (unused by reference)
    const float* opac    = (const float*)d_in[2];
    const float* colors  = (const float*)d_in[3];
    const float* scales  = (const float*)d_in[4];
    const float* rots    = (const float*)d_in[5];
    const float* bg      = (const float*)d_in[6];
    const float* vm      = (const float*)d_in[7];
    const float* pm      = (const float*)d_in[8];
    float* out = (float*)d_out;

    int P = in_sizes[0] / 3;
    if (P > PMAX) P = PMAX;

    const int tiles = (IMG_W / TILE) * (IMG_H / TILE);
    fused_kernel<<<tiles, TILE * TILE>>>(means3D, opac, colors, scales, rots,
                                         vm, pm, bg, out, P);
}